// round 1
// baseline (speedup 1.0000x reference)
#include <cuda_runtime.h>
#include <math.h>

#define BB 8
#define NN 2048
#define DD 128
#define NEG 0.2f
#define BN (BB*NN)

#define TILE_N 16
#define CHUNK 64
#define HPAD 132
#define APAD 68

// scratch (device globals — no allocations allowed)
__device__ float g_h[BN*DD];          // 8 MB
__device__ float g_si[BN];
__device__ float g_sj[BN];
__device__ unsigned g_adj[NN*(NN/32)]; // packed adjacency bitmask

// ---------------- pack adjacency into bitmask ----------------
__global__ void k_pack(const int* __restrict__ adj) {
    int row = blockIdx.x;
    int lane = threadIdx.x & 31, w0 = threadIdx.x >> 5;
    for (int w = w0; w < NN/32; w += 8) {
        int v = adj[row*NN + w*32 + lane];
        unsigned bits = __ballot_sync(0xffffffffu, v > 0);
        if (lane == 0) g_adj[row*(NN/32) + w] = bits;
    }
}

// ---------------- h = x @ W ----------------
// block: 128 threads (one per output col), 32 rows per block
__global__ void k_h(const float* __restrict__ x, const float* __restrict__ W) {
    __shared__ float xs[32*128];
    int tid = threadIdx.x;
    int row0 = blockIdx.x * 32;
    for (int i = tid; i < 32*128; i += 128) xs[i] = x[(size_t)row0*128 + i];
    __syncthreads();
    float acc[32];
#pragma unroll
    for (int r = 0; r < 32; r++) acc[r] = 0.f;
#pragma unroll 2
    for (int k = 0; k < 128; k++) {
        float wv = W[k*128 + tid];
#pragma unroll
        for (int r = 0; r < 32; r++) acc[r] += xs[r*128 + k] * wv;
    }
#pragma unroll
    for (int r = 0; r < 32; r++) g_h[(size_t)(row0 + r)*128 + tid] = acc[r];
}

// ---------------- s_i = h@a1, s_j = h@a2 ----------------
// block 256 = 8 warps, one row per warp
__global__ void k_s(const float* __restrict__ a_vec) {
    int warp = threadIdx.x >> 5, lane = threadIdx.x & 31;
    int row = blockIdx.x * 8 + warp;
    float4 h4 = *(const float4*)(g_h + (size_t)row*128 + lane*4);
    float4 a14 = *(const float4*)(a_vec + lane*4);
    float4 a24 = *(const float4*)(a_vec + 128 + lane*4);
    float s1 = h4.x*a14.x + h4.y*a14.y + h4.z*a14.z + h4.w*a14.w;
    float s2 = h4.x*a24.x + h4.y*a24.y + h4.z*a24.z + h4.w*a24.w;
#pragma unroll
    for (int o = 16; o; o >>= 1) {
        s1 += __shfl_xor_sync(0xffffffffu, s1, o);
        s2 += __shfl_xor_sync(0xffffffffu, s2, o);
    }
    if (lane == 0) { g_si[row] = s1; g_sj[row] = s2; }
}

// ---------------- fused softmax + alpha write + out = alpha@h ----------------
// grid: (N/TILE_N, B), block 256
__global__ void __launch_bounds__(256) k_main(float* __restrict__ out,
                                              float* __restrict__ alpha) {
    extern __shared__ float smem[];
    float* sj_sh   = smem;                         // 2048
    float* al_sh   = sj_sh + NN;                   // TILE_N*APAD
    float* h_sh    = al_sh + TILE_N*APAD;          // CHUNK*HPAD
    float* si_sh   = h_sh + CHUNK*HPAD;            // 16
    float* rmax_sh = si_sh + TILE_N;               // 16
    float* rinv_sh = rmax_sh + TILE_N;             // 16
    unsigned* adj_sh = (unsigned*)(rinv_sh + TILE_N); // TILE_N*64 words

    int b = blockIdx.y;
    int n0 = blockIdx.x * TILE_N;
    int tid = threadIdx.x;
    int warp = tid >> 5, lane = tid & 31;

    for (int i = tid; i < NN; i += 256) sj_sh[i] = g_sj[b*NN + i];
    for (int i = tid; i < TILE_N*64; i += 256)
        adj_sh[i] = g_adj[(size_t)(n0 + (i >> 6))*64 + (i & 63)];
    if (tid < TILE_N) si_sh[tid] = g_si[b*NN + n0 + tid];
    __syncthreads();

    // pass A (max via monotonic leaky-relu) + pass B (sum), warp-per-row
    for (int rr = warp; rr < TILE_N; rr += 8) {
        float si = si_sh[rr];
        float mx = -1e30f;
        for (int wq = lane; wq < 64; wq += 32) {
            unsigned bits = adj_sh[rr*64 + wq];
            int base = wq*32;
#pragma unroll
            for (int j = 0; j < 32; j++)
                if (bits & (1u << j)) mx = fmaxf(mx, sj_sh[base + j]);
        }
#pragma unroll
        for (int o = 16; o; o >>= 1) mx = fmaxf(mx, __shfl_xor_sync(0xffffffffu, mx, o));
        float t = si + mx;
        float emax = t >= 0.f ? t : NEG * t;

        float sum = 0.f;
        for (int wq = lane; wq < 64; wq += 32) {
            unsigned bits = adj_sh[rr*64 + wq];
            int base = wq*32;
#pragma unroll
            for (int j = 0; j < 32; j++)
                if (bits & (1u << j)) {
                    float v = si + sj_sh[base + j];
                    float e = v >= 0.f ? v : NEG * v;
                    sum += __expf(e - emax);
                }
        }
#pragma unroll
        for (int o = 16; o; o >>= 1) sum += __shfl_xor_sync(0xffffffffu, sum, o);
        if (lane == 0) { rmax_sh[rr] = emax; rinv_sh[rr] = 1.f / sum; }
    }
    __syncthreads();

    // pass C: per 64-wide m-chunk: compute alpha (write gmem + smem), then FMA into out
    float acc[8];
#pragma unroll
    for (int i = 0; i < 8; i++) acc[i] = 0.f;
    int grp  = tid >> 7;      // 0..1  -> n block of 8
    int dcol = tid & 127;     // output column
    int mloc = tid & 63;      // alpha-phase column within chunk
    int r0   = tid >> 6;      // 0..3  -> alpha-phase row group

    for (int m0 = 0; m0 < NN; m0 += CHUNK) {
        // stage h[b, m0:m0+CHUNK, :] (row-major, padded)
        for (int i = tid; i < CHUNK*32; i += 256) {
            int mi = i >> 5, q = i & 31;
            float4 v = *(const float4*)(g_h + (size_t)(b*NN + m0 + mi)*DD + q*4);
            *(float4*)(h_sh + mi*HPAD + q*4) = v;
        }
        // compute alpha sub-tile: TILE_N x CHUNK
        int m = m0 + mloc;
        float sj = sj_sh[m];
        int wq = m >> 5, bitpos = m & 31;
#pragma unroll
        for (int rr = r0; rr < TILE_N; rr += 4) {
            float v = si_sh[rr] + sj;
            float e = v >= 0.f ? v : NEG * v;
            unsigned bits = adj_sh[rr*64 + wq];
            float a = ((bits >> bitpos) & 1u)
                        ? __expf(e - rmax_sh[rr]) * rinv_sh[rr] : 0.f;
            al_sh[rr*APAD + mloc] = a;
            alpha[((size_t)(b*NN + n0 + rr))*NN + m] = a;
        }
        __syncthreads();
        // accumulate out tile
#pragma unroll 4
        for (int mi = 0; mi < CHUNK; mi += 4) {
            float h0 = h_sh[(mi+0)*HPAD + dcol];
            float h1 = h_sh[(mi+1)*HPAD + dcol];
            float h2 = h_sh[(mi+2)*HPAD + dcol];
            float h3 = h_sh[(mi+3)*HPAD + dcol];
#pragma unroll
            for (int i = 0; i < 8; i++) {
                float4 a4 = *(const float4*)(al_sh + (grp*8 + i)*APAD + mi);
                acc[i] += a4.x*h0;
                acc[i] += a4.y*h1;
                acc[i] += a4.z*h2;
                acc[i] += a4.w*h3;
            }
        }
        __syncthreads();
    }
#pragma unroll
    for (int i = 0; i < 8; i++)
        out[((size_t)(b*NN + n0 + grp*8 + i))*DD + dcol] = acc[i];
}

// ---------------- launch ----------------
extern "C" void kernel_launch(void* const* d_in, const int* in_sizes, int n_in,
                              void* d_out, int out_size) {
    const float* x    = (const float*)d_in[0];
    const int*   adj  = (const int*)  d_in[1];
    const float* W    = (const float*)d_in[2];
    const float* avec = (const float*)d_in[3];
    float* out   = (float*)d_out;
    float* alpha = out + (size_t)BN*DD;

    static const int SMEM_MAIN =
        (NN + TILE_N*APAD + CHUNK*HPAD + 3*TILE_N + TILE_N*64) * 4;
    cudaFuncSetAttribute(k_main, cudaFuncAttributeMaxDynamicSharedMemorySize,
                         SMEM_MAIN);

    k_pack<<<NN, 256>>>(adj);
    k_h<<<BN/32, 128>>>(x, W);
    k_s<<<BN/8, 256>>>(avec);
    dim3 grid(NN/TILE_N, BB);
    k_main<<<grid, 256, SMEM_MAIN>>>(out, alpha);
}

// round 2
// speedup vs baseline: 1.6594x; 1.6594x over previous
#include <cuda_runtime.h>
#include <math.h>

#define BB 8
#define NN 2048
#define DD 128
#define NEG 0.2f
#define BN (BB*NN)

#define TILE_N 32
#define CHUNK 64
#define APITCH 36

// scratch (device globals — no allocations allowed)
__device__ float  g_h[BN*DD];            // 8 MB
__device__ float  g_eA[BN];              // exp(s_i)
__device__ float  g_eC[BN];              // exp(0.2 s_i)
__device__ float2 g_e12[BN];             // {exp(s_j), exp(0.2 s_j)}
__device__ unsigned g_adj[NN*(NN/32)];   // packed adjacency bitmask

// ---------------- f32x2 packed helpers ----------------
__device__ __forceinline__ unsigned long long pk2(float v) {
    unsigned long long r;
    asm("mov.b64 %0, {%1, %1};" : "=l"(r) : "f"(v));
    return r;
}
__device__ __forceinline__ void fma2(unsigned long long& d,
                                     unsigned long long a,
                                     unsigned long long b) {
    asm("fma.rn.f32x2 %0, %1, %2, %3;" : "=l"(d) : "l"(a), "l"(b), "l"(d));
}
__device__ __forceinline__ float2 upk(unsigned long long v) {
    float2 f;
    asm("mov.b64 {%0, %1}, %2;" : "=f"(f.x), "=f"(f.y) : "l"(v));
    return f;
}

// ---------------- pack adjacency into bitmask ----------------
__global__ void k_pack(const int* __restrict__ adj) {
    int row = blockIdx.x;
    int lane = threadIdx.x & 31, w0 = threadIdx.x >> 5;
    for (int w = w0; w < NN/32; w += 8) {
        int v = adj[row*NN + w*32 + lane];
        unsigned bits = __ballot_sync(0xffffffffu, v > 0);
        if (lane == 0) g_adj[row*(NN/32) + w] = bits;
    }
}

// ---------------- h = x @ W ----------------
__global__ void k_h(const float* __restrict__ x, const float* __restrict__ W) {
    __shared__ float xs[32*128];
    int tid = threadIdx.x;
    int row0 = blockIdx.x * 32;
    for (int i = tid; i < 32*128; i += 128) xs[i] = x[(size_t)row0*128 + i];
    __syncthreads();
    float acc[32];
#pragma unroll
    for (int r = 0; r < 32; r++) acc[r] = 0.f;
#pragma unroll 2
    for (int k = 0; k < 128; k++) {
        float wv = W[k*128 + tid];
#pragma unroll
        for (int r = 0; r < 32; r++) acc[r] += xs[r*128 + k] * wv;
    }
#pragma unroll
    for (int r = 0; r < 32; r++) g_h[(size_t)(row0 + r)*128 + tid] = acc[r];
}

// ---------------- s_i, s_j -> exp arrays ----------------
__global__ void k_s(const float* __restrict__ a_vec) {
    int warp = threadIdx.x >> 5, lane = threadIdx.x & 31;
    int row = blockIdx.x * 8 + warp;
    float4 h4  = *(const float4*)(g_h + (size_t)row*128 + lane*4);
    float4 a14 = *(const float4*)(a_vec + lane*4);
    float4 a24 = *(const float4*)(a_vec + 128 + lane*4);
    float s1 = h4.x*a14.x + h4.y*a14.y + h4.z*a14.z + h4.w*a14.w;
    float s2 = h4.x*a24.x + h4.y*a24.y + h4.z*a24.z + h4.w*a24.w;
#pragma unroll
    for (int o = 16; o; o >>= 1) {
        s1 += __shfl_xor_sync(0xffffffffu, s1, o);
        s2 += __shfl_xor_sync(0xffffffffu, s2, o);
    }
    if (lane == 0) {
        g_eA[row] = __expf(s1);
        g_eC[row] = __expf(NEG * s1);
        g_e12[row] = make_float2(__expf(s2), __expf(NEG * s2));
    }
}

// ---------------- fused softmax + alpha write + out = alpha@h ----------------
// grid (NN/TILE_N, BB), block 256
__global__ void __launch_bounds__(256, 4) k_main(float* __restrict__ out,
                                                 float* __restrict__ alpha) {
    extern __shared__ float smem[];
    float*    h_sh   = smem;                          // CHUNK*128 = 8192
    float*    al_sh  = h_sh + CHUNK*128;              // CHUNK*APITCH = 2304
    unsigned* adj_sh = (unsigned*)(al_sh + CHUNK*APITCH); // TILE_N*64 = 2048
    float*    eA_sh  = (float*)(adj_sh + TILE_N*64);  // 32
    float*    eC_sh  = eA_sh + TILE_N;                // 32
    float*    rinv_sh= eC_sh + TILE_N;                // 32

    int b   = blockIdx.y;
    int n0  = blockIdx.x * TILE_N;
    int tid = threadIdx.x;
    int warp = tid >> 5, lane = tid & 31;

    for (int i = tid; i < TILE_N*64; i += 256)
        adj_sh[i] = g_adj[(size_t)(n0 + (i >> 6))*64 + (i & 63)];
    if (tid < TILE_N) {
        eA_sh[tid] = g_eA[b*NN + n0 + tid];
        eC_sh[tid] = g_eC[b*NN + n0 + tid];
    }
    __syncthreads();

    // ---- pass B: row sums (warp per row, 4 rows per warp) ----
    const float2* e12 = g_e12 + b*NN;
#pragma unroll
    for (int k = 0; k < 4; k++) {
        int rr = warp*4 + k;
        float Ai = eA_sh[rr], Ci = eC_sh[rr];
        float sum = 0.f;
        const unsigned* arow = adj_sh + rr*64;
        for (int it = 0; it < 64; it++) {
            unsigned bits = arow[it];
            float2 ev = e12[it*32 + lane];
            float nu = fmaxf(Ai*ev.x, Ci*ev.y);
            sum += ((bits >> lane) & 1u) ? nu : 0.f;
        }
#pragma unroll
        for (int o = 16; o; o >>= 1) sum += __shfl_xor_sync(0xffffffffu, sum, o);
        if (lane == 0) rinv_sh[rr] = 1.f / sum;
    }
    __syncthreads();

    // ---- pass C ----
    int mloc = tid & 63, rb = tid >> 6;   // alpha-phase mapping
    int c2 = tid & 63,  rg = tid >> 6;    // FMA-phase mapping (cols 2c2,2c2+1; rows rg*8..+7)

    unsigned long long acc[8];
#pragma unroll
    for (int i = 0; i < 8; i++) acc[i] = 0ull;

    for (int m0 = 0; m0 < NN; m0 += CHUNK) {
        // stage h[b, m0:m0+CHUNK, :]
#pragma unroll
        for (int i = 0; i < 8; i++) {
            int idx = tid + i*256;
            int mi = idx >> 5, q = idx & 31;
            *(float4*)(h_sh + mi*128 + q*4) =
                *(const float4*)(g_h + ((size_t)(b*NN + m0 + mi))*128 + q*4);
        }
        // compute alpha sub-tile TILE_N x CHUNK (transposed in smem) + gmem write
        {
            int m = m0 + mloc;
            float2 ev = e12[m];
            int widx = m >> 5;
            int bitp = m & 31;
            float av[8];
#pragma unroll
            for (int r = 0; r < 8; r++) {
                int rr = rb*8 + r;
                float nu = fmaxf(eA_sh[rr]*ev.x, eC_sh[rr]*ev.y);
                unsigned bits = adj_sh[rr*64 + widx];
                float a = ((bits >> bitp) & 1u) ? nu * rinv_sh[rr] : 0.f;
                av[r] = a;
                alpha[((size_t)(b*NN + n0 + rr))*NN + m] = a;
            }
            *(float4*)(al_sh + mloc*APITCH + rb*8)     = make_float4(av[0],av[1],av[2],av[3]);
            *(float4*)(al_sh + mloc*APITCH + rb*8 + 4) = make_float4(av[4],av[5],av[6],av[7]);
        }
        __syncthreads();

        // FMA: out[rg*8..+7][2c2,2c2+1] += alpha^T chunk @ h chunk
        const float* hp = h_sh + 2*c2;
        const float* ap = al_sh + rg*8;
#pragma unroll 8
        for (int mi = 0; mi < CHUNK; mi++) {
            float2 hv = *(const float2*)(hp + mi*128);
            unsigned long long hx = pk2(hv.x), hy = pk2(hv.y);
            ulonglong2 pA = *(const ulonglong2*)(ap + mi*APITCH);
            ulonglong2 pB = *(const ulonglong2*)(ap + mi*APITCH + 4);
            fma2(acc[0], pA.x, hx); fma2(acc[1], pA.x, hy);
            fma2(acc[2], pA.y, hx); fma2(acc[3], pA.y, hy);
            fma2(acc[4], pB.x, hx); fma2(acc[5], pB.x, hy);
            fma2(acc[6], pB.y, hx); fma2(acc[7], pB.y, hy);
        }
        __syncthreads();
    }

    // store out: pairs p=0..3 -> rows rg*8+2p, rg*8+2p+1 ; cols 2c2, 2c2+1
    float* op = out + ((size_t)(b*NN + n0 + rg*8))*128 + 2*c2;
#pragma unroll
    for (int p = 0; p < 4; p++) {
        float2 rc0 = upk(acc[2*p]);     // col 2c2   : rows (2p, 2p+1)
        float2 rc1 = upk(acc[2*p + 1]); // col 2c2+1 : rows (2p, 2p+1)
        *(float2*)(op + (size_t)(2*p)*128)     = make_float2(rc0.x, rc1.x);
        *(float2*)(op + (size_t)(2*p + 1)*128) = make_float2(rc0.y, rc1.y);
    }
}

// ---------------- launch ----------------
extern "C" void kernel_launch(void* const* d_in, const int* in_sizes, int n_in,
                              void* d_out, int out_size) {
    const float* x    = (const float*)d_in[0];
    const int*   adj  = (const int*)  d_in[1];
    const float* W    = (const float*)d_in[2];
    const float* avec = (const float*)d_in[3];
    float* out   = (float*)d_out;
    float* alpha = out + (size_t)BN*DD;

    static const int SMEM_MAIN =
        (CHUNK*128 + CHUNK*APITCH + TILE_N*64 + 3*TILE_N) * 4;
    cudaFuncSetAttribute(k_main, cudaFuncAttributeMaxDynamicSharedMemorySize,
                         SMEM_MAIN);

    k_pack<<<NN, 256>>>(adj);
    k_h<<<BN/32, 128>>>(x, W);
    k_s<<<BN/8, 256>>>(avec);
    dim3 grid(NN/TILE_N, BB);
    k_main<<<grid, 256, SMEM_MAIN>>>(out, alpha);
}

// round 6
// speedup vs baseline: 2.9749x; 1.7927x over previous
#include <cuda_runtime.h>
#include <cuda_bf16.h>
#include <cstdint>

#define BB 8
#define NN 2048
#define DD 128
#define NEG 0.2f
#define BN (BB*NN)

#define KCHUNK 64
#define NCHUNKS (NN/KCHUNK)   // 32

// ---------------- scratch (device globals) ----------------
__device__ unsigned short g_hT1[(size_t)BB*DD*NN];  // bf16 hi part of h^T [b][d][m]
__device__ unsigned short g_hT2[(size_t)BB*DD*NN];  // bf16 residual part
__device__ float  g_eA[BN];              // exp(s_i)
__device__ float  g_eC[BN];              // exp(0.2 s_i)
__device__ float2 g_e12[BN];             // {exp(s_j), exp(0.2 s_j)}
__device__ unsigned g_adj[NN*(NN/32)];   // packed adjacency bitmask

// ---------------- helpers ----------------
__device__ __forceinline__ uint32_t smem_to_u32(const void* p) {
    uint32_t a;
    asm("{ .reg .u64 t; cvta.to.shared.u64 t, %1; cvt.u32.u64 %0, t; }"
        : "=r"(a) : "l"(p));
    return a;
}
#define SW128(off) ((off) ^ (((off) >> 3) & 0x70))

__device__ __forceinline__ void ldsm4(uint32_t* r, uint32_t addr) {
    asm volatile("ldmatrix.sync.aligned.m8n8.x4.shared.b16 {%0,%1,%2,%3}, [%4];"
        : "=r"(r[0]), "=r"(r[1]), "=r"(r[2]), "=r"(r[3]) : "r"(addr));
}
__device__ __forceinline__ void mma_bf16(float* c, const uint32_t* a,
                                         uint32_t b0, uint32_t b1) {
    asm volatile(
        "mma.sync.aligned.m16n8k16.row.col.f32.bf16.bf16.f32 "
        "{%0,%1,%2,%3}, {%4,%5,%6,%7}, {%8,%9}, {%0,%1,%2,%3};"
        : "+f"(c[0]), "+f"(c[1]), "+f"(c[2]), "+f"(c[3])
        : "r"(a[0]), "r"(a[1]), "r"(a[2]), "r"(a[3]), "r"(b0), "r"(b1));
}

// bf16 2-term split: p1 = bf16x2(a0,a1) (lo=a0), p2 = bf16x2 of residuals
__device__ __forceinline__ void bsplit(float a0, float a1, unsigned& p1, unsigned& p2) {
    asm("cvt.rn.bf16x2.f32 %0, %2, %1;" : "=r"(p1) : "f"(a0), "f"(a1));
    float b0 = __uint_as_float(p1 << 16);
    float b1 = __uint_as_float(p1 & 0xffff0000u);
    float r0 = a0 - b0, r1 = a1 - b1;
    asm("cvt.rn.bf16x2.f32 %0, %2, %1;" : "=r"(p2) : "f"(r0), "f"(r1));
}

// ---------------- pack adjacency into bitmask ----------------
__global__ void k_pack(const int* __restrict__ adj) {
    int row = blockIdx.x;
    int lane = threadIdx.x & 31, w0 = threadIdx.x >> 5;
    for (int w = w0; w < NN/32; w += 8) {
        int v = adj[row*NN + w*32 + lane];
        unsigned bits = __ballot_sync(0xffffffffu, v > 0);
        if (lane == 0) g_adj[row*(NN/32) + w] = bits;
    }
}

// ---------------- h = x@W -> hT bf16 splits + s/exp arrays ----------------
__global__ void k_h(const float* __restrict__ x, const float* __restrict__ W,
                    const float* __restrict__ a_vec) {
    __shared__ float xs[32*128];
    int tid = threadIdx.x;
    int row0 = blockIdx.x * 32;
    for (int i = tid; i < 32*128; i += 128) xs[i] = x[(size_t)row0*128 + i];
    __syncthreads();
    float acc[32];
#pragma unroll
    for (int r = 0; r < 32; r++) acc[r] = 0.f;
#pragma unroll 2
    for (int k = 0; k < 128; k++) {
        float wv = W[k*128 + tid];
#pragma unroll
        for (int r = 0; r < 32; r++) acc[r] += xs[r*128 + k] * wv;
    }
    // write hT bf16 split: thread = d column, rows = 32 consecutive m
    int b = row0 >> 11;
    int mbase = row0 & 2047;
    {
        unsigned u1[16], u2[16];
#pragma unroll
        for (int k = 0; k < 16; k++) bsplit(acc[2*k], acc[2*k+1], u1[k], u2[k]);
        size_t base = ((size_t)(b*DD + tid) * NN + mbase) >> 1;  // uint32 units
        uint4* d1 = (uint4*)((unsigned*)g_hT1 + base);
        uint4* d2 = (uint4*)((unsigned*)g_hT2 + base);
#pragma unroll
        for (int k = 0; k < 4; k++) {
            d1[k] = *(uint4*)(u1 + 4*k);
            d2[k] = *(uint4*)(u2 + 4*k);
        }
    }
    // s reduction (reuse xs)
    __syncthreads();
#pragma unroll
    for (int r = 0; r < 32; r++) xs[r*128 + tid] = acc[r];
    __syncthreads();
    int warp = tid >> 5, lane = tid & 31;
    float4 a14 = *(const float4*)(a_vec + lane*4);
    float4 a24 = *(const float4*)(a_vec + 128 + lane*4);
#pragma unroll
    for (int k = 0; k < 8; k++) {
        int r = warp*8 + k;
        float4 hv = *(const float4*)(xs + r*128 + lane*4);
        float s1 = hv.x*a14.x + hv.y*a14.y + hv.z*a14.z + hv.w*a14.w;
        float s2 = hv.x*a24.x + hv.y*a24.y + hv.z*a24.z + hv.w*a24.w;
#pragma unroll
        for (int o = 16; o; o >>= 1) {
            s1 += __shfl_xor_sync(0xffffffffu, s1, o);
            s2 += __shfl_xor_sync(0xffffffffu, s2, o);
        }
        if (lane == 0) {
            int gr = row0 + r;
            g_eA[gr] = __expf(s1);
            g_eC[gr] = __expf(NEG * s1);
            g_e12[gr] = make_float2(__expf(s2), __expf(NEG * s2));
        }
    }
}

// ---------------- smem layout ----------------
#define SM_A1   0u
#define SM_A2   16384u
#define SM_B1   32768u
#define SM_B2   49152u
#define SM_E12  65536u      // 16 KB
#define SM_ADJ  81920u      // 32 KB
#define SM_ROW  114688u     // = SM_ADJ + 32768 (NO overlap)
#define SM_TOTAL (114688 + 1536)

// ---------------- fused softmax + alpha + HMMA alpha@h ----------------
// grid (16, 8), block 256 (8 warps)
__global__ void __launch_bounds__(256, 1) k_main(float* __restrict__ out,
                                                 float* __restrict__ alpha) {
    extern __shared__ __align__(1024) char smem[];
    uint32_t sb = smem_to_u32(smem);
    int tid = threadIdx.x, wid = tid >> 5, lane = tid & 31;
    int b = blockIdx.y, n0 = blockIdx.x * 128;

    float*    e12f = (float*)(smem + SM_E12);
    unsigned* adjs = (unsigned*)(smem + SM_ADJ);
    float* AiSh = (float*)(smem + SM_ROW);
    float* CiSh = AiSh + 128;
    float* RvSh = CiSh + 128;

    // stage e12 (16KB) and adj bitmask (32KB)
    {
        const uint4* s = (const uint4*)(g_e12 + b*NN);
        uint4* d = (uint4*)e12f;
#pragma unroll
        for (int k = 0; k < 4; k++) d[tid + k*256] = s[tid + k*256];
    }
    {
        const uint4* s = (const uint4*)(g_adj + (size_t)n0*64);
        uint4* d = (uint4*)adjs;
#pragma unroll
        for (int k = 0; k < 8; k++) d[tid + k*256] = s[tid + k*256];
    }
    if (tid < 128) {
        AiSh[tid] = g_eA[b*NN + n0 + tid];
        CiSh[tid] = g_eC[b*NN + n0 + tid];
    }
    __syncthreads();

    // ---- pass B: row softmax denominators (16 rows per warp) ----
    for (int k = 0; k < 16; k++) {
        int r = wid*16 + k;
        float Ai = AiSh[r], Ci = CiSh[r];
        const unsigned* arow = adjs + r*64;
        float sum = 0.f;
#pragma unroll 4
        for (int i2 = 0; i2 < 32; i2++) {
            float4 ev = *(const float4*)(e12f + i2*128 + lane*4);
            unsigned bits = arow[i2*2 + (lane >> 4)];
            unsigned bp = (lane & 15) * 2;
            float nu0 = fmaxf(Ai*ev.x, Ci*ev.y);
            float nu1 = fmaxf(Ai*ev.z, Ci*ev.w);
            sum += ((bits >> bp) & 1u) ? nu0 : 0.f;
            sum += ((bits >> (bp+1)) & 1u) ? nu1 : 0.f;
        }
#pragma unroll
        for (int o = 16; o; o >>= 1) sum += __shfl_xor_sync(0xffffffffu, sum, o);
        if (lane == 0) RvSh[r] = 1.f / sum;
    }
    __syncthreads();

    // per-thread alpha mapping: row = tid>>1, half (32 m) = tid&1
    int arw = tid >> 1, mhalf = tid & 1;
    float Ai = AiSh[arw], Ci = CiSh[arw], Rv = RvSh[arw];
    float* aout = alpha + ((size_t)(b*NN + n0 + arw)) * NN;

    // B staging: 4 rows per thread per split (rows brow+32i, 8 uint4 per row)
    int brow = tid >> 3, bq = tid & 7;
    size_t gbase = ((size_t)(b*128 + brow))*256 + bq;     // uint4 units
    unsigned bsw = SW128((unsigned)(brow*128 + bq*16));
    const uint4* gB1 = (const uint4*)g_hT1;
    const uint4* gB2 = (const uint4*)g_hT2;

    // warp GEMM tiling: warp -> n-tile 64, d-tile 32
    int n0w = (wid >> 2) * 64, d0w = (wid & 3) * 32;
    int arow_l = lane & 15;
    unsigned acol_l = (lane >> 4) * 16;
    int brow_l = (lane & 7) + ((lane >> 4) << 3);
    unsigned bcol_l = ((lane >> 3) & 1) * 16;
    // swizzle = row*128 + (col ^ ((row&7)<<4)); row advances of 16 keep row&7
    unsigned a_xor = (unsigned)((arow_l & 7) << 4);
    unsigned b_xor = (unsigned)((brow_l & 7) << 4);
    uint32_t a_row_base = sb + SM_A1 + (unsigned)((n0w + arow_l) * 128);
    uint32_t b_row_base = sb + SM_B1 + (unsigned)((d0w + brow_l) * 128);

    float acc[4][4][4];   // [ngroup16][d8tile][reg]
#pragma unroll
    for (int i = 0; i < 4; i++)
#pragma unroll
        for (int j = 0; j < 4; j++)
#pragma unroll
            for (int k = 0; k < 4; k++) acc[i][j][k] = 0.f;

    // prefetch chunk 0
    uint4 v1[4], v2[4];
#pragma unroll
    for (int i = 0; i < 4; i++) {
        v1[i] = gB1[gbase + (size_t)i*8192];
        v2[i] = gB2[gbase + (size_t)i*8192];
    }

    for (int c = 0; c < NCHUNKS; c++) {
        int m0 = c * KCHUNK;
        // STS B tiles
#pragma unroll
        for (int i = 0; i < 4; i++) {
            *(uint4*)(smem + SM_B1 + bsw + i*4096) = v1[i];
            *(uint4*)(smem + SM_B2 + bsw + i*4096) = v2[i];
        }
        // alpha: 32 m per thread (exact fp32 STG + bf16 split STS into A tiles)
        unsigned bits = adjs[arw*64 + c*2 + mhalf];
#pragma unroll
        for (int g = 0; g < 8; g++) {
            int mloc = mhalf*32 + g*4;
            int m = m0 + mloc;
            float4 e01 = *(const float4*)(e12f + 2*m);
            float4 e23 = *(const float4*)(e12f + 2*m + 4);
            float n0v = fmaxf(Ai*e01.x, Ci*e01.y);
            float n1v = fmaxf(Ai*e01.z, Ci*e01.w);
            float n2v = fmaxf(Ai*e23.x, Ci*e23.y);
            float n3v = fmaxf(Ai*e23.z, Ci*e23.w);
            unsigned bp = g*4;
            float a0 = ((bits >> (bp+0)) & 1u) ? n0v*Rv : 0.f;
            float a1 = ((bits >> (bp+1)) & 1u) ? n1v*Rv : 0.f;
            float a2 = ((bits >> (bp+2)) & 1u) ? n2v*Rv : 0.f;
            float a3 = ((bits >> (bp+3)) & 1u) ? n3v*Rv : 0.f;
            *(float4*)(aout + m) = make_float4(a0, a1, a2, a3);
            unsigned p1a, p2a, p1b, p2b;
            bsplit(a0, a1, p1a, p2a);
            bsplit(a2, a3, p1b, p2b);
            unsigned so = SW128((unsigned)(arw*128 + mloc*2));
            *(uint2*)(smem + SM_A1 + so) = make_uint2(p1a, p1b);
            *(uint2*)(smem + SM_A2 + so) = make_uint2(p2a, p2b);
        }
        __syncthreads();

        // prefetch next chunk (hidden under the MMA phase)
        if (c + 1 < NCHUNKS) {
            size_t mo = (size_t)((m0 + KCHUNK) >> 3);
#pragma unroll
            for (int i = 0; i < 4; i++) {
                v1[i] = gB1[gbase + (size_t)i*8192 + mo];
                v2[i] = gB2[gbase + (size_t)i*8192 + mo];
            }
        }

        // MMA phase: 4 k-steps of 16
#pragma unroll
        for (int ks = 0; ks < 4; ks++) {
            unsigned acol = (acol_l + ks*32) ^ a_xor;   // swizzled column
            unsigned bcol = (bcol_l + ks*32) ^ b_xor;
            uint32_t a1f[4][4], a2f[4][4], b1f[2][4], b2f[2][4];
#pragma unroll
            for (int ng = 0; ng < 4; ng++) {
                ldsm4(a1f[ng], a_row_base + ng*2048 + acol);
                ldsm4(a2f[ng], a_row_base + ng*2048 + acol + (SM_A2 - SM_A1));
            }
#pragma unroll
            for (int dg = 0; dg < 2; dg++) {
                ldsm4(b1f[dg], b_row_base + dg*2048 + bcol);
                ldsm4(b2f[dg], b_row_base + dg*2048 + bcol + (SM_B2 - SM_B1));
            }
#pragma unroll
            for (int ng = 0; ng < 4; ng++) {
#pragma unroll
                for (int dg = 0; dg < 2; dg++) {
                    mma_bf16(acc[ng][dg*2+0], a1f[ng], b1f[dg][0], b1f[dg][1]);
                    mma_bf16(acc[ng][dg*2+1], a1f[ng], b1f[dg][2], b1f[dg][3]);
                    mma_bf16(acc[ng][dg*2+0], a1f[ng], b2f[dg][0], b2f[dg][1]);
                    mma_bf16(acc[ng][dg*2+1], a1f[ng], b2f[dg][2], b2f[dg][3]);
                    mma_bf16(acc[ng][dg*2+0], a2f[ng], b1f[dg][0], b1f[dg][1]);
                    mma_bf16(acc[ng][dg*2+1], a2f[ng], b1f[dg][2], b1f[dg][3]);
                }
            }
        }
        __syncthreads();
    }

    // epilogue: write out tile
#pragma unroll
    for (int ng = 0; ng < 4; ng++) {
#pragma unroll
        for (int dt = 0; dt < 4; dt++) {
            int r = n0 + n0w + ng*16 + (lane >> 2);
            int col = d0w + dt*8 + (lane & 3)*2;
            float* p = out + ((size_t)(b*NN + r))*DD + col;
            *(float2*)p = make_float2(acc[ng][dt][0], acc[ng][dt][1]);
            *(float2*)(p + 8*DD) = make_float2(acc[ng][dt][2], acc[ng][dt][3]);
        }
    }
}

// ---------------- launch ----------------
extern "C" void kernel_launch(void* const* d_in, const int* in_sizes, int n_in,
                              void* d_out, int out_size) {
    const float* x    = (const float*)d_in[0];
    const int*   adj  = (const int*)  d_in[1];
    const float* W    = (const float*)d_in[2];
    const float* avec = (const float*)d_in[3];
    float* out   = (float*)d_out;
    float* alpha = out + (size_t)BN*DD;

    cudaFuncSetAttribute(k_main, cudaFuncAttributeMaxDynamicSharedMemorySize,
                         SM_TOTAL);

    k_pack<<<NN, 256>>>(adj);
    k_h<<<BN/32, 128>>>(x, W, avec);
    dim3 grid(NN/128, BB);
    k_main<<<grid, 256, SM_TOTAL>>>(out, alpha);
}